// round 8
// baseline (speedup 1.0000x reference)
#include <cuda_runtime.h>
#include <math.h>

#define Bb 4
#define Cc 256
#define Nn 4096
#define Mm 4096
#define Hh 4
#define Dd 64

// Scratch (allocation-free rule: __device__ globals)
__device__ float g_Q[Bb * Cc * Nn];
__device__ float g_K[Bb * Cc * Mm];
__device__ float g_V[Bb * Cc * Mm];
__device__ float g_O[Bb * Cc * Nn];

// ---------------------------------------------------------------------------
// Pointwise-conv projection: out[b][o][l] = sum_c W[o][c]*x[b][c][l] + bias[o]
// 128x128 tile, k-step 16, 256 threads, 8x8 microtile (split 4+4 halves).
// grid: (L/128, Cc/128, Bb)
// ---------------------------------------------------------------------------
__global__ __launch_bounds__(256, 2) void proj_kernel(
    const float* __restrict__ W, const float* __restrict__ bias,
    const float* __restrict__ x, float* __restrict__ out, int L)
{
    __shared__ float sW[16 * 132];   // [k][o], pitch 132
    __shared__ float sX[16 * 132];   // [k][l], pitch 132

    const int tid = threadIdx.x;
    const int l0 = blockIdx.x * 128;
    const int o0 = blockIdx.y * 128;
    const int b  = blockIdx.z;
    const float* xb = x + (size_t)b * Cc * L;

    const int ty = tid >> 4, tx = tid & 15;
    const int wo = tid >> 1, whalf = tid & 1;   // W-load: 2 threads per o-row

    float acc[8][8] = {};

    for (int k0 = 0; k0 < Cc; k0 += 16) {
        // Load W tile (transposed into sW[k][o])
        {
            const float* wr = &W[(size_t)(o0 + wo) * Cc + k0 + whalf * 8];
            float4 w0 = *(const float4*)&wr[0];
            float4 w1 = *(const float4*)&wr[4];
            int kb = whalf * 8;
            sW[(kb + 0) * 132 + wo] = w0.x;
            sW[(kb + 1) * 132 + wo] = w0.y;
            sW[(kb + 2) * 132 + wo] = w0.z;
            sW[(kb + 3) * 132 + wo] = w0.w;
            sW[(kb + 4) * 132 + wo] = w1.x;
            sW[(kb + 5) * 132 + wo] = w1.y;
            sW[(kb + 6) * 132 + wo] = w1.z;
            sW[(kb + 7) * 132 + wo] = w1.w;
        }
        // Load X tile (direct, coalesced)
        #pragma unroll
        for (int u = 0; u < 2; u++) {
            int f4 = tid + u * 256;
            int xk = f4 >> 5, xl4 = (f4 & 31) * 4;
            *(float4*)&sX[xk * 132 + xl4] =
                *(const float4*)&xb[(size_t)(k0 + xk) * L + l0 + xl4];
        }
        __syncthreads();

        #pragma unroll
        for (int k = 0; k < 16; k++) {
            float4 al = *(const float4*)&sW[k * 132 + ty * 4];
            float4 ah = *(const float4*)&sW[k * 132 + 64 + ty * 4];
            float4 bl = *(const float4*)&sX[k * 132 + tx * 4];
            float4 bh = *(const float4*)&sX[k * 132 + 64 + tx * 4];
            float av[8] = {al.x, al.y, al.z, al.w, ah.x, ah.y, ah.z, ah.w};
            float bv[8] = {bl.x, bl.y, bl.z, bl.w, bh.x, bh.y, bh.z, bh.w};
            #pragma unroll
            for (int i = 0; i < 8; i++)
                #pragma unroll
                for (int j = 0; j < 8; j++)
                    acc[i][j] += av[i] * bv[j];
        }
        __syncthreads();
    }

    #pragma unroll
    for (int i = 0; i < 8; i++) {
        int orow = o0 + ((i < 4) ? (ty * 4 + i) : (64 + ty * 4 + (i - 4)));
        float bi = bias[orow];
        float* orow_p = &out[(size_t)(b * Cc + orow) * L + l0];
        *(float4*)&orow_p[tx * 4] = make_float4(
            acc[i][0] + bi, acc[i][1] + bi, acc[i][2] + bi, acc[i][3] + bi);
        *(float4*)&orow_p[64 + tx * 4] = make_float4(
            acc[i][4] + bi, acc[i][5] + bi, acc[i][6] + bi, acc[i][7] + bi);
    }
}

// ---------------------------------------------------------------------------
// Flash attention (fp32). CTA = (b, h, 128-query tile); loop over 128-key
// tiles. Stage A: S = Q^T K / 8 (8x8 microtile). Online softmax. Stage C:
// O += P V^T (4dx8n microtile). P tile stored with XOR swizzle.
// grid: (Nn/128, Hh, Bb), 256 threads, ~165KB dynamic smem.
// ---------------------------------------------------------------------------
#define QS_OFF 0
#define KS_OFF (64 * 128)
#define VS_OFF (KS_OFF + 64 * 128)           // Vs[m][d], pitch 68
#define PT_OFF (VS_OFF + 128 * 68)           // Pt[m][n], pitch 132, swizzled
#define MR_OFF (PT_OFF + 128 * 132)
#define LR_OFF (MR_OFF + 128)
#define AR_OFF (LR_OFF + 128)
#define SM_FLOATS (AR_OFF + 128)

__global__ __launch_bounds__(256, 1) void attn_kernel(
    const float* __restrict__ Qg, const float* __restrict__ Kg,
    const float* __restrict__ Vg, float* __restrict__ Og)
{
    extern __shared__ float sm[];
    float* Qs = sm + QS_OFF;
    float* Ks = sm + KS_OFF;
    float* Vs = sm + VS_OFF;
    float* Pt = sm + PT_OFF;
    float* mrow = sm + MR_OFF;
    float* lrow = sm + LR_OFF;
    float* arow = sm + AR_OFF;

    const int tid = threadIdx.x;
    const int n0 = blockIdx.x * 128;
    const int h = blockIdx.y, b = blockIdx.z;
    const size_t hb = (size_t)(b * Cc + h * Dd);
    const float* Qh = Qg + hb * Nn;
    const float* Kh = Kg + hb * Mm;
    const float* Vh = Vg + hb * Mm;
    float* Oh = Og + hb * Nn;

    // Load Q tile: Qs[d][n], pitch 128 (coalesced)
    #pragma unroll
    for (int u = 0; u < 8; u++) {
        int f4 = tid + u * 256;
        int d = f4 >> 5, n4 = (f4 & 31) * 4;
        *(float4*)&Qs[d * 128 + n4] =
            *(const float4*)&Qh[(size_t)d * Nn + n0 + n4];
    }
    if (tid < 128) { mrow[tid] = -1e30f; lrow[tid] = 0.f; }

    const int ty = tid >> 4, tx = tid & 15;   // stage A map
    const int d0 = ty * 4, nx = tx;           // stage C map (reuse split)
    const int nrow = tid >> 1, part = tid & 1;// softmax map

    float oacc[4][8] = {};   // [i over d0+i][j: j<4 -> nx*4+j, j>=4 -> 64+nx*4+j-4]

    for (int mt = 0; mt < Mm; mt += 128) {
        // Load K tile Ks[d][m] (coalesced)
        #pragma unroll
        for (int u = 0; u < 8; u++) {
            int f4 = tid + u * 256;
            int d = f4 >> 5, m4 = (f4 & 31) * 4;
            *(float4*)&Ks[d * 128 + m4] =
                *(const float4*)&Kh[(size_t)d * Mm + mt + m4];
        }
        // Load V transposed into Vs[m][d] via 4x4 register blocks.
        // blk: lanes span d-group -> conflict-free STS.128.
        #pragma unroll
        for (int u = 0; u < 2; u++) {
            int blk = tid + u * 256;
            int d0v = (blk & 15) * 4;
            int mi  = (blk >> 4) * 4;
            float4 r0 = *(const float4*)&Vh[(size_t)(d0v + 0) * Mm + mt + mi];
            float4 r1 = *(const float4*)&Vh[(size_t)(d0v + 1) * Mm + mt + mi];
            float4 r2 = *(const float4*)&Vh[(size_t)(d0v + 2) * Mm + mt + mi];
            float4 r3 = *(const float4*)&Vh[(size_t)(d0v + 3) * Mm + mt + mi];
            *(float4*)&Vs[(mi + 0) * 68 + d0v] = make_float4(r0.x, r1.x, r2.x, r3.x);
            *(float4*)&Vs[(mi + 1) * 68 + d0v] = make_float4(r0.y, r1.y, r2.y, r3.y);
            *(float4*)&Vs[(mi + 2) * 68 + d0v] = make_float4(r0.z, r1.z, r2.z, r3.z);
            *(float4*)&Vs[(mi + 3) * 68 + d0v] = make_float4(r0.w, r1.w, r2.w, r3.w);
        }
        __syncthreads();

        // ---- Stage A: S[n=128][m=128], 8x8 microtile ----
        {
            float s[8][8] = {};
            #pragma unroll 4
            for (int k = 0; k < 64; k++) {
                const float* qr = &Qs[k * 128];
                const float* kr = &Ks[k * 128];
                float4 ql = *(const float4*)&qr[ty * 4];
                float4 qh2 = *(const float4*)&qr[64 + ty * 4];
                float4 kl = *(const float4*)&kr[tx * 4];
                float4 kh2 = *(const float4*)&kr[64 + tx * 4];
                float qv[8] = {ql.x, ql.y, ql.z, ql.w, qh2.x, qh2.y, qh2.z, qh2.w};
                float kv[8] = {kl.x, kl.y, kl.z, kl.w, kh2.x, kh2.y, kh2.z, kh2.w};
                #pragma unroll
                for (int i = 0; i < 8; i++)
                    #pragma unroll
                    for (int j = 0; j < 8; j++)
                        s[i][j] += qv[i] * kv[j];
            }
            // Store S/8 transposed into swizzled Pt[m][n]
            const int swz = tx & 7;
            const int blo = ty ^ swz;
            #pragma unroll
            for (int j = 0; j < 8; j++) {
                int mv = (j < 4) ? (tx * 4 + j) : (64 + tx * 4 + (j - 4));
                float4* row = (float4*)&Pt[mv * 132];
                row[blo] = make_float4(s[0][j] * 0.125f, s[1][j] * 0.125f,
                                       s[2][j] * 0.125f, s[3][j] * 0.125f);
                row[16 + blo] = make_float4(s[4][j] * 0.125f, s[5][j] * 0.125f,
                                            s[6][j] * 0.125f, s[7][j] * 0.125f);
            }
        }
        __syncthreads();

        // ---- Stage B: online softmax (2 threads per query row) ----
        {
            float mloc = -1e30f;
            #pragma unroll 8
            for (int s2 = 0; s2 < 64; s2++) {
                int mv = part * 64 + s2;
                int sw = (mv >> 2) & 7;
                float v = Pt[mv * 132 + ((((nrow >> 2) ^ sw) << 2) | (nrow & 3))];
                mloc = fmaxf(mloc, v);
            }
            mloc = fmaxf(mloc, __shfl_xor_sync(0xffffffffu, mloc, 1));
            float mprev = mrow[nrow];
            float mnew = fmaxf(mprev, mloc);
            float sum = 0.f;
            #pragma unroll 8
            for (int s2 = 0; s2 < 64; s2++) {
                int mv = part * 64 + s2;
                int sw = (mv >> 2) & 7;
                int idx = mv * 132 + ((((nrow >> 2) ^ sw) << 2) | (nrow & 3));
                float e = __expf(Pt[idx] - mnew);
                Pt[idx] = e;
                sum += e;
            }
            sum += __shfl_xor_sync(0xffffffffu, sum, 1);
            if (part == 0) {
                float a = __expf(mprev - mnew);
                arow[nrow] = a;
                lrow[nrow] = lrow[nrow] * a + sum;
                mrow[nrow] = mnew;
            }
        }
        __syncthreads();

        // ---- Stage C: O[d][n] += P V^T, rescale by arow ----
        {
            float4 al = *(const float4*)&arow[nx * 4];
            float4 ah = *(const float4*)&arow[64 + nx * 4];
            float av[8] = {al.x, al.y, al.z, al.w, ah.x, ah.y, ah.z, ah.w};
            #pragma unroll
            for (int i = 0; i < 4; i++)
                #pragma unroll
                for (int j = 0; j < 8; j++)
                    oacc[i][j] *= av[j];

            #pragma unroll 4
            for (int m = 0; m < 128; m++) {
                float4 v = *(const float4*)&Vs[m * 68 + d0];
                int sw = (m >> 2) & 7;
                const float4* pr = (const float4*)&Pt[m * 132];
                float4 pl = pr[nx ^ sw];
                float4 ph = pr[16 + (nx ^ sw)];
                float vv[4] = {v.x, v.y, v.z, v.w};
                float pv[8] = {pl.x, pl.y, pl.z, pl.w, ph.x, ph.y, ph.z, ph.w};
                #pragma unroll
                for (int i = 0; i < 4; i++)
                    #pragma unroll
                    for (int j = 0; j < 8; j++)
                        oacc[i][j] += vv[i] * pv[j];
            }
        }
        __syncthreads();
    }

    // Epilogue: divide by l, store (coalesced over n)
    {
        float4 ll = *(const float4*)&lrow[nx * 4];
        float4 lh = *(const float4*)&lrow[64 + nx * 4];
        float inv[8] = {1.f / ll.x, 1.f / ll.y, 1.f / ll.z, 1.f / ll.w,
                        1.f / lh.x, 1.f / lh.y, 1.f / lh.z, 1.f / lh.w};
        #pragma unroll
        for (int i = 0; i < 4; i++) {
            float* orow_p = &Oh[(size_t)(d0 + i) * Nn + n0];
            *(float4*)&orow_p[nx * 4] = make_float4(
                oacc[i][0] * inv[0], oacc[i][1] * inv[1],
                oacc[i][2] * inv[2], oacc[i][3] * inv[3]);
            *(float4*)&orow_p[64 + nx * 4] = make_float4(
                oacc[i][4] * inv[4], oacc[i][5] * inv[5],
                oacc[i][6] * inv[6], oacc[i][7] * inv[7]);
        }
    }
}

// ---------------------------------------------------------------------------
extern "C" void kernel_launch(void* const* d_in, const int* in_sizes, int n_in,
                              void* d_out, int out_size)
{
    const float* query  = (const float*)d_in[0];
    const float* source = (const float*)d_in[1];
    const float* Wq = (const float*)d_in[2];
    const float* bq = (const float*)d_in[3];
    const float* Wk = (const float*)d_in[4];
    const float* bk = (const float*)d_in[5];
    const float* Wv = (const float*)d_in[6];
    const float* bv = (const float*)d_in[7];
    const float* Wm = (const float*)d_in[8];
    const float* bm = (const float*)d_in[9];
    float* out = (float*)d_out;

    float *pQ, *pK, *pV, *pO;
    cudaGetSymbolAddress((void**)&pQ, g_Q);
    cudaGetSymbolAddress((void**)&pK, g_K);
    cudaGetSymbolAddress((void**)&pV, g_V);
    cudaGetSymbolAddress((void**)&pO, g_O);

    const int smem = SM_FLOATS * (int)sizeof(float);
    cudaFuncSetAttribute(attn_kernel,
                         cudaFuncAttributeMaxDynamicSharedMemorySize, smem);

    dim3 gq(Nn / 128, Cc / 128, Bb);
    dim3 gs(Mm / 128, Cc / 128, Bb);
    dim3 ga(Nn / 128, Hh, Bb);

    proj_kernel<<<gq, 256>>>(Wq, bq, query,  pQ, Nn);
    proj_kernel<<<gs, 256>>>(Wk, bk, source, pK, Mm);
    proj_kernel<<<gs, 256>>>(Wv, bv, source, pV, Mm);
    attn_kernel<<<ga, 256, smem>>>(pQ, pK, pV, pO);
    proj_kernel<<<gq, 256>>>(Wm, bm, pO, out, Nn);
}

// round 9
// speedup vs baseline: 1.1934x; 1.1934x over previous
#include <cuda_runtime.h>
#include <math.h>

#define Bb 4
#define Cc 256
#define Nn 4096
#define Mm 4096
#define Hh 4
#define Dd 64

// Scratch (allocation-free rule: __device__ globals)
__device__ float g_Q[Bb * Cc * Nn];
__device__ float g_K[Bb * Cc * Mm];
__device__ float g_V[Bb * Cc * Mm];
__device__ float g_O[Bb * Cc * Nn];

typedef unsigned long long u64;

// ---- packed f32x2 helpers (Blackwell FFMA2 path) ----
__device__ __forceinline__ u64 ffma2(u64 a, u64 b, u64 c) {
    u64 d;
    asm("fma.rn.f32x2 %0, %1, %2, %3;" : "=l"(d) : "l"(a), "l"(b), "l"(c));
    return d;
}
__device__ __forceinline__ u64 fmul2(u64 a, u64 b) {
    u64 d;
    asm("mul.rn.f32x2 %0, %1, %2;" : "=l"(d) : "l"(a), "l"(b));
    return d;
}
__device__ __forceinline__ u64 pack2(float x) {
    u64 r;
    unsigned xi = __float_as_uint(x);
    asm("mov.b64 %0, {%1, %1};" : "=l"(r) : "r"(xi));
    return r;
}
__device__ __forceinline__ float2 unpack2(u64 v) {
    float2 r;
    asm("mov.b64 {%0, %1}, %2;" : "=f"(r.x), "=f"(r.y) : "l"(v));
    return r;
}

// ---------------------------------------------------------------------------
// Pointwise-conv projection: out[b][o][l] = sum_c W[o][c]*x[b][c][l] + bias[o]
// 128x128 tile, k-step 16, 256 threads, 8x8 microtile. (unchanged, proven)
// ---------------------------------------------------------------------------
__global__ __launch_bounds__(256, 2) void proj_kernel(
    const float* __restrict__ W, const float* __restrict__ bias,
    const float* __restrict__ x, float* __restrict__ out, int L)
{
    __shared__ float sW[16 * 132];
    __shared__ float sX[16 * 132];

    const int tid = threadIdx.x;
    const int l0 = blockIdx.x * 128;
    const int o0 = blockIdx.y * 128;
    const int b  = blockIdx.z;
    const float* xb = x + (size_t)b * Cc * L;

    const int ty = tid >> 4, tx = tid & 15;
    const int wo = tid >> 1, whalf = tid & 1;

    float acc[8][8] = {};

    for (int k0 = 0; k0 < Cc; k0 += 16) {
        {
            const float* wr = &W[(size_t)(o0 + wo) * Cc + k0 + whalf * 8];
            float4 w0 = *(const float4*)&wr[0];
            float4 w1 = *(const float4*)&wr[4];
            int kb = whalf * 8;
            sW[(kb + 0) * 132 + wo] = w0.x;
            sW[(kb + 1) * 132 + wo] = w0.y;
            sW[(kb + 2) * 132 + wo] = w0.z;
            sW[(kb + 3) * 132 + wo] = w0.w;
            sW[(kb + 4) * 132 + wo] = w1.x;
            sW[(kb + 5) * 132 + wo] = w1.y;
            sW[(kb + 6) * 132 + wo] = w1.z;
            sW[(kb + 7) * 132 + wo] = w1.w;
        }
        #pragma unroll
        for (int u = 0; u < 2; u++) {
            int f4 = tid + u * 256;
            int xk = f4 >> 5, xl4 = (f4 & 31) * 4;
            *(float4*)&sX[xk * 132 + xl4] =
                *(const float4*)&xb[(size_t)(k0 + xk) * L + l0 + xl4];
        }
        __syncthreads();

        #pragma unroll
        for (int k = 0; k < 16; k++) {
            float4 al = *(const float4*)&sW[k * 132 + ty * 4];
            float4 ah = *(const float4*)&sW[k * 132 + 64 + ty * 4];
            float4 bl = *(const float4*)&sX[k * 132 + tx * 4];
            float4 bh = *(const float4*)&sX[k * 132 + 64 + tx * 4];
            float av[8] = {al.x, al.y, al.z, al.w, ah.x, ah.y, ah.z, ah.w};
            float bv[8] = {bl.x, bl.y, bl.z, bl.w, bh.x, bh.y, bh.z, bh.w};
            #pragma unroll
            for (int i = 0; i < 8; i++)
                #pragma unroll
                for (int j = 0; j < 8; j++)
                    acc[i][j] += av[i] * bv[j];
        }
        __syncthreads();
    }

    #pragma unroll
    for (int i = 0; i < 8; i++) {
        int orow = o0 + ((i < 4) ? (ty * 4 + i) : (64 + ty * 4 + (i - 4)));
        float bi = bias[orow];
        float* orow_p = &out[(size_t)(b * Cc + orow) * L + l0];
        *(float4*)&orow_p[tx * 4] = make_float4(
            acc[i][0] + bi, acc[i][1] + bi, acc[i][2] + bi, acc[i][3] + bi);
        *(float4*)&orow_p[64 + tx * 4] = make_float4(
            acc[i][4] + bi, acc[i][5] + bi, acc[i][6] + bi, acc[i][7] + bi);
    }
}

// ---------------------------------------------------------------------------
// Flash attention, fp32 math via packed fma.rn.f32x2 (FFMA2).
// CTA = (b, h, 128-query tile); 128-key tiles. Register online softmax.
// grid: (Nn/128, Hh, Bb), 256 threads, ~165KB dynamic smem.
// ---------------------------------------------------------------------------
#define QS_OFF 0
#define KS_OFF (64 * 128)
#define VS_OFF (KS_OFF + 64 * 128)           // Vs[m][d], pitch 68
#define PT_OFF (VS_OFF + 128 * 68)           // Pt[m][n], pitch 132, swizzled
#define AR_OFF (PT_OFF + 128 * 132)          // arow[128]
#define LR_OFF (AR_OFF + 128)                // lrow[128]
#define SM_FLOATS (LR_OFF + 128)

__global__ __launch_bounds__(256, 1) void attn_kernel(
    const float* __restrict__ Qg, const float* __restrict__ Kg,
    const float* __restrict__ Vg, float* __restrict__ Og)
{
    extern __shared__ float sm[];
    float* Qs = sm + QS_OFF;
    float* Ks = sm + KS_OFF;
    float* Vs = sm + VS_OFF;
    float* Pt = sm + PT_OFF;
    float* arow = sm + AR_OFF;
    float* lrow = sm + LR_OFF;

    const int tid = threadIdx.x;
    const int n0 = blockIdx.x * 128;
    const int h = blockIdx.y, b = blockIdx.z;
    const size_t hb = (size_t)(b * Cc + h * Dd);
    const float* Qh = Qg + hb * Nn;
    const float* Kh = Kg + hb * Mm;
    const float* Vh = Vg + hb * Mm;
    float* Oh = Og + hb * Nn;

    // Load Q tile: Qs[d][n], pitch 128 (coalesced)
    #pragma unroll
    for (int u = 0; u < 8; u++) {
        int f4 = tid + u * 256;
        int d = f4 >> 5, n4 = (f4 & 31) * 4;
        *(float4*)&Qs[d * 128 + n4] =
            *(const float4*)&Qh[(size_t)d * Nn + n0 + n4];
    }

    const int ty = tid >> 4, tx = tid & 15;   // stage A map
    const int d0 = ty * 4, nx = tx;           // stage C map

    // Register-resident running softmax state (identical across the 16 lanes
    // of each ty-row; i<4 -> n=ty*4+i, i>=4 -> n=64+ty*4+i-4)
    float rm[8], rl[8];
    #pragma unroll
    for (int i = 0; i < 8; i++) { rm[i] = -1e30f; rl[i] = 0.f; }

    u64 oacc[4][4];   // packed pairs over n: [i over d0+i][jp]
    #pragma unroll
    for (int i = 0; i < 4; i++)
        #pragma unroll
        for (int jp = 0; jp < 4; jp++) oacc[i][jp] = 0ull;

    for (int mt = 0; mt < Mm; mt += 128) {
        // Load K tile Ks[d][m] (coalesced)
        #pragma unroll
        for (int u = 0; u < 8; u++) {
            int f4 = tid + u * 256;
            int d = f4 >> 5, m4 = (f4 & 31) * 4;
            *(float4*)&Ks[d * 128 + m4] =
                *(const float4*)&Kh[(size_t)d * Mm + mt + m4];
        }
        // Load V transposed into Vs[m][d] via 4x4 register blocks
        #pragma unroll
        for (int u = 0; u < 2; u++) {
            int blk = tid + u * 256;
            int d0v = (blk & 15) * 4;
            int mi  = (blk >> 4) * 4;
            float4 r0 = *(const float4*)&Vh[(size_t)(d0v + 0) * Mm + mt + mi];
            float4 r1 = *(const float4*)&Vh[(size_t)(d0v + 1) * Mm + mt + mi];
            float4 r2 = *(const float4*)&Vh[(size_t)(d0v + 2) * Mm + mt + mi];
            float4 r3 = *(const float4*)&Vh[(size_t)(d0v + 3) * Mm + mt + mi];
            *(float4*)&Vs[(mi + 0) * 68 + d0v] = make_float4(r0.x, r1.x, r2.x, r3.x);
            *(float4*)&Vs[(mi + 1) * 68 + d0v] = make_float4(r0.y, r1.y, r2.y, r3.y);
            *(float4*)&Vs[(mi + 2) * 68 + d0v] = make_float4(r0.z, r1.z, r2.z, r3.z);
            *(float4*)&Vs[(mi + 3) * 68 + d0v] = make_float4(r0.w, r1.w, r2.w, r3.w);
        }
        __syncthreads();

        // ---- Stage A: S = Q^T K via FFMA2, 8n x 8m per thread ----
        u64 s2[8][4];
        #pragma unroll
        for (int i = 0; i < 8; i++)
            #pragma unroll
            for (int jp = 0; jp < 4; jp++) s2[i][jp] = 0ull;

        #pragma unroll 4
        for (int k = 0; k < 64; k++) {
            const float* qr = &Qs[k * 128];
            const float* kr = &Ks[k * 128];
            float4 ql = *(const float4*)&qr[ty * 4];
            float4 qh2 = *(const float4*)&qr[64 + ty * 4];
            ulonglong2 kA = *(const ulonglong2*)&kr[tx * 4];        // (m0,m1),(m2,m3)
            ulonglong2 kB = *(const ulonglong2*)&kr[64 + tx * 4];   // (m4,m5),(m6,m7)
            float qf[8] = {ql.x, ql.y, ql.z, ql.w, qh2.x, qh2.y, qh2.z, qh2.w};
            #pragma unroll
            for (int i = 0; i < 8; i++) {
                u64 qq = pack2(qf[i]);
                s2[i][0] = ffma2(qq, kA.x, s2[i][0]);
                s2[i][1] = ffma2(qq, kA.y, s2[i][1]);
                s2[i][2] = ffma2(qq, kB.x, s2[i][2]);
                s2[i][3] = ffma2(qq, kB.y, s2[i][3]);
            }
        }

        // ---- Register online softmax (per ty-row, 16-lane shfl reduce) ----
        float e[8][8];
        float aval[8];
        #pragma unroll
        for (int i = 0; i < 8; i++) {
            float sr[8];
            #pragma unroll
            for (int jp = 0; jp < 4; jp++) {
                float2 p = unpack2(s2[i][jp]);
                sr[2 * jp] = p.x; sr[2 * jp + 1] = p.y;
            }
            float tmax = sr[0];
            #pragma unroll
            for (int j = 1; j < 8; j++) tmax = fmaxf(tmax, sr[j]);
            tmax = fmaxf(tmax, __shfl_xor_sync(0xffffffffu, tmax, 1));
            tmax = fmaxf(tmax, __shfl_xor_sync(0xffffffffu, tmax, 2));
            tmax = fmaxf(tmax, __shfl_xor_sync(0xffffffffu, tmax, 4));
            tmax = fmaxf(tmax, __shfl_xor_sync(0xffffffffu, tmax, 8));
            float mnew = fmaxf(rm[i], tmax * 0.125f);
            float a = __expf(rm[i] - mnew);
            float sum = 0.f;
            #pragma unroll
            for (int j = 0; j < 8; j++) {
                float ev = __expf(fmaf(sr[j], 0.125f, -mnew));
                e[i][j] = ev;
                sum += ev;
            }
            sum += __shfl_xor_sync(0xffffffffu, sum, 1);
            sum += __shfl_xor_sync(0xffffffffu, sum, 2);
            sum += __shfl_xor_sync(0xffffffffu, sum, 4);
            sum += __shfl_xor_sync(0xffffffffu, sum, 8);
            rl[i] = rl[i] * a + sum;
            rm[i] = mnew;
            aval[i] = a;
        }

        // Store P (exp'ed) transposed into swizzled Pt[m][n]
        {
            const int swz = tx & 7;
            const int blo = ty ^ swz;
            #pragma unroll
            for (int j = 0; j < 8; j++) {
                int mv = (j < 4) ? (tx * 4 + j) : (64 + tx * 4 + (j - 4));
                float4* row = (float4*)&Pt[mv * 132];
                row[blo] = make_float4(e[0][j], e[1][j], e[2][j], e[3][j]);
                row[16 + blo] = make_float4(e[4][j], e[5][j], e[6][j], e[7][j]);
            }
        }
        // arow for stage C rescale (one lane per row writes)
        if (tx == 0) {
            #pragma unroll
            for (int i = 0; i < 4; i++) arow[ty * 4 + i] = aval[i];
            #pragma unroll
            for (int i = 4; i < 8; i++) arow[64 + ty * 4 + (i - 4)] = aval[i];
        }
        __syncthreads();

        // ---- Stage C: O[d][n] += P V^T via FFMA2, rescale by arow ----
        {
            ulonglong2 aA = *(const ulonglong2*)&arow[nx * 4];
            ulonglong2 aB = *(const ulonglong2*)&arow[64 + nx * 4];
            u64 ap[4] = {aA.x, aA.y, aB.x, aB.y};
            #pragma unroll
            for (int i = 0; i < 4; i++)
                #pragma unroll
                for (int jp = 0; jp < 4; jp++)
                    oacc[i][jp] = fmul2(oacc[i][jp], ap[jp]);

            #pragma unroll 4
            for (int m = 0; m < 128; m++) {
                float4 v = *(const float4*)&Vs[m * 68 + d0];
                int sw = (m >> 2) & 7;
                const float4* pr = (const float4*)&Pt[m * 132];
                ulonglong2 pA = *(const ulonglong2*)&pr[nx ^ sw];
                ulonglong2 pB = *(const ulonglong2*)&pr[16 + (nx ^ sw)];
                float vf[4] = {v.x, v.y, v.z, v.w};
                #pragma unroll
                for (int i = 0; i < 4; i++) {
                    u64 vv = pack2(vf[i]);
                    oacc[i][0] = ffma2(vv, pA.x, oacc[i][0]);
                    oacc[i][1] = ffma2(vv, pA.y, oacc[i][1]);
                    oacc[i][2] = ffma2(vv, pB.x, oacc[i][2]);
                    oacc[i][3] = ffma2(vv, pB.y, oacc[i][3]);
                }
            }
        }
        __syncthreads();
    }

    // Publish l per row, then epilogue divide + store
    if (tx == 0) {
        #pragma unroll
        for (int i = 0; i < 4; i++) lrow[ty * 4 + i] = rl[i];
        #pragma unroll
        for (int i = 4; i < 8; i++) lrow[64 + ty * 4 + (i - 4)] = rl[i];
    }
    __syncthreads();
    {
        float4 ll = *(const float4*)&lrow[nx * 4];
        float4 lh = *(const float4*)&lrow[64 + nx * 4];
        float inv[8] = {1.f / ll.x, 1.f / ll.y, 1.f / ll.z, 1.f / ll.w,
                        1.f / lh.x, 1.f / lh.y, 1.f / lh.z, 1.f / lh.w};
        #pragma unroll
        for (int i = 0; i < 4; i++) {
            float of[8];
            #pragma unroll
            for (int jp = 0; jp < 4; jp++) {
                float2 p = unpack2(oacc[i][jp]);
                of[2 * jp] = p.x; of[2 * jp + 1] = p.y;
            }
            float* orow_p = &Oh[(size_t)(d0 + i) * Nn + n0];
            *(float4*)&orow_p[nx * 4] = make_float4(
                of[0] * inv[0], of[1] * inv[1], of[2] * inv[2], of[3] * inv[3]);
            *(float4*)&orow_p[64 + nx * 4] = make_float4(
                of[4] * inv[4], of[5] * inv[5], of[6] * inv[6], of[7] * inv[7]);
        }
    }
}

// ---------------------------------------------------------------------------
extern "C" void kernel_launch(void* const* d_in, const int* in_sizes, int n_in,
                              void* d_out, int out_size)
{
    const float* query  = (const float*)d_in[0];
    const float* source = (const float*)d_in[1];
    const float* Wq = (const float*)d_in[2];
    const float* bq = (const float*)d_in[3];
    const float* Wk = (const float*)d_in[4];
    const float* bk = (const float*)d_in[5];
    const float* Wv = (const float*)d_in[6];
    const float* bv = (const float*)d_in[7];
    const float* Wm = (const float*)d_in[8];
    const float* bm = (const float*)d_in[9];
    float* out = (float*)d_out;

    float *pQ, *pK, *pV, *pO;
    cudaGetSymbolAddress((void**)&pQ, g_Q);
    cudaGetSymbolAddress((void**)&pK, g_K);
    cudaGetSymbolAddress((void**)&pV, g_V);
    cudaGetSymbolAddress((void**)&pO, g_O);

    const int smem = SM_FLOATS * (int)sizeof(float);
    cudaFuncSetAttribute(attn_kernel,
                         cudaFuncAttributeMaxDynamicSharedMemorySize, smem);

    dim3 gq(Nn / 128, Cc / 128, Bb);
    dim3 gs(Mm / 128, Cc / 128, Bb);
    dim3 ga(Nn / 128, Hh, Bb);

    proj_kernel<<<gq, 256>>>(Wq, bq, query,  pQ, Nn);
    proj_kernel<<<gs, 256>>>(Wk, bk, source, pK, Mm);
    proj_kernel<<<gs, 256>>>(Wv, bv, source, pV, Mm);
    attn_kernel<<<ga, 256, smem>>>(pQ, pK, pV, pO);
    proj_kernel<<<gq, 256>>>(Wm, bm, pO, out, Nn);
}